// round 12
// baseline (speedup 1.0000x reference)
#include <cuda_runtime.h>
#include <cuda_fp16.h>
#include <cstdint>

#define HID 128
#define NN 50000
#define NE 800000
#define T_TILES 5
// byte strides (all ≡16 mod 128 -> ldmatrix conflict-free)
#define SA_STR 272   // sH / sE rows: 136 halves (also 68 floats for staging)
#define EF_STR 144   // sEF rows
#define EW_STR 144
#define W1_STR 528
#define W2_STR 272

extern __shared__ char dyn_smem[];

// ---------------- device scratch (allocation-free rule) ----------------
__device__ __half g_h[(size_t)NN * HID];
__device__ float  g_agg[(size_t)NN * HID];
__device__ __half g_nWt[128 * 128];
__device__ __half g_eWt[128 * 64];
__device__ __half g_W1t[128 * 256];
__device__ __half g_W2t[128 * 128];
__device__ __half g_U1t[128 * 256];
__device__ __half g_U2t[128 * 128];

// ======================= helpers (generic PTX) =========================
__device__ __forceinline__ uint32_t smem_u32(const void* p) {
    uint32_t a;
    asm("{ .reg .u64 t; cvta.to.shared.u64 t, %1; cvt.u32.u64 %0, t; }"
        : "=r"(a) : "l"(p));
    return a;
}
__device__ __forceinline__ void ldsm4(uint32_t r[4], uint32_t addr) {
    asm volatile("ldmatrix.sync.aligned.m8n8.x4.shared.b16 {%0,%1,%2,%3}, [%4];"
                 : "=r"(r[0]), "=r"(r[1]), "=r"(r[2]), "=r"(r[3]) : "r"(addr));
}
__device__ __forceinline__ void mma16(float c[4], const uint32_t a[4],
                                      uint32_t b0, uint32_t b1) {
    asm volatile("mma.sync.aligned.m16n8k16.row.col.f32.f16.f16.f32 "
                 "{%0,%1,%2,%3}, {%4,%5,%6,%7}, {%8,%9}, {%0,%1,%2,%3};"
                 : "+f"(c[0]), "+f"(c[1]), "+f"(c[2]), "+f"(c[3])
                 : "r"(a[0]), "r"(a[1]), "r"(a[2]), "r"(a[3]), "r"(b0), "r"(b1));
}
#define CP16(dst, src) \
    asm volatile("cp.async.cg.shared.global [%0], [%1], 16;" :: "r"(dst), "l"(src))
#define CP_COMMIT() asm volatile("cp.async.commit_group;" ::: "memory")
#define CP_WAIT(n)  asm volatile("cp.async.wait_group %0;" :: "n"(n) : "memory")
// TMA-style bulk reduce (sm_90 base feature)
#define BULK_RED_F32(gptr, saddr, bytes) \
    asm volatile("cp.reduce.async.bulk.global.shared::cta.bulk_group.add.f32 " \
                 "[%0], [%1], %2;" :: "l"(gptr), "r"(saddr), "r"(bytes) : "memory")
#define BULK_COMMIT()   asm volatile("cp.async.bulk.commit_group;" ::: "memory")
#define BULK_WAIT_RD0() asm volatile("cp.async.bulk.wait_group.read 0;" ::: "memory")
#define BULK_WAIT0()    asm volatile("cp.async.bulk.wait_group 0;" ::: "memory")
#define FENCE_ASYNC()   asm volatile("fence.proxy.async.shared::cta;" ::: "memory")

__device__ __forceinline__ void zacc(float acc[2][4][4]) {
#pragma unroll
    for (int i = 0; i < 2; ++i)
#pragma unroll
        for (int j = 0; j < 4; ++j)
#pragma unroll
            for (int k = 0; k < 4; ++k) acc[i][j][k] = 0.f;
}

template <int KSTEPS>
__device__ __forceinline__ void wgemm(uint32_t aA0, uint32_t aA1,
                                      const uint32_t bA[2], float acc[2][4][4]) {
#pragma unroll
    for (int ks = 0; ks < KSTEPS; ++ks) {
        uint32_t a0[4], a1[4];
        ldsm4(a0, aA0 + ks * 32);
        ldsm4(a1, aA1 + ks * 32);
#pragma unroll
        for (int jj = 0; jj < 2; ++jj) {
            uint32_t b[4];
            ldsm4(b, bA[jj] + ks * 32);
            mma16(acc[0][2 * jj],     a0, b[0], b[1]);
            mma16(acc[0][2 * jj + 1], a0, b[2], b[3]);
            mma16(acc[1][2 * jj],     a1, b[0], b[1]);
            mma16(acc[1][2 * jj + 1], a1, b[2], b[3]);
        }
    }
}

__device__ __forceinline__ uint32_t a_off(int lane, int strideB) {
    int row = (lane & 7) + ((lane & 8) ? 8 : 0);
    return (uint32_t)row * strideB + ((lane & 16) ? 16 : 0);
}
__device__ __forceinline__ uint32_t b_off(int lane, int strideB) {
    int row = (lane & 7) + ((lane & 16) ? 8 : 0);
    return (uint32_t)row * strideB + ((lane & 8) ? 16 : 0);
}

template <int KH>
__device__ __forceinline__ void stage_w(uint32_t dstB, int dstStr,
                                        const __half* srcBase, int srcK, int tid) {
    constexpr int SEGS = KH / 8;
#pragma unroll
    for (int i = tid; i < 128 * SEGS; i += 512) {
        int n = i / SEGS, s = i % SEGS;
        CP16(dstB + (uint32_t)(n * dstStr + s * 16),
             srcBase + (size_t)n * srcK + s * 8);
    }
}

// ---------------------------------------------------------------------------
__global__ void k_tW(const float* __restrict__ nW, const float* __restrict__ eW,
                     const float* __restrict__ W1, const float* __restrict__ W2,
                     const float* __restrict__ U1, const float* __restrict__ U2) {
    int t = blockIdx.x * blockDim.x + threadIdx.x;
    int tot = gridDim.x * blockDim.x;
    for (int i = t; i < 128 * 128; i += tot) {
        int n = i >> 7, k = i & 127;
        g_nWt[i] = __float2half_rn(nW[k * 128 + n]);
        g_W2t[i] = __float2half_rn(W2[k * 128 + n]);
        g_U2t[i] = __float2half_rn(U2[k * 128 + n]);
    }
    for (int i = t; i < 128 * 64; i += tot) {
        int n = i >> 6, k = i & 63;
        g_eWt[i] = __float2half_rn(eW[k * 128 + n]);
    }
    for (int i = t; i < 128 * 256; i += tot) {
        int n = i >> 8, k = i & 255;
        g_W1t[i] = __float2half_rn(W1[k * 128 + n]);
        g_U1t[i] = __float2half_rn(U1[k * 128 + n]);
    }
}

__global__ __launch_bounds__(256) void k_zero_agg() {
    size_t i = (size_t)blockIdx.x * 256 + threadIdx.x;
    reinterpret_cast<float4*>(g_agg)[i] = make_float4(0.f, 0.f, 0.f, 0.f);
}

// ---------------------------------------------------------------------------
// Kernel 1: h = fp16(node_feats @ node_W + node_b) -> g_h
// ---------------------------------------------------------------------------
static constexpr int NODE_SA = 0;
static constexpr int NODE_SB = 128 * SA_STR;
static constexpr int NODE_BIAS = NODE_SB + 128 * SA_STR;
static constexpr int NODE_SMEM = NODE_BIAS + 512;

__global__ __launch_bounds__(512, 1) void k_node(const float* __restrict__ nf,
                                                 const float* __restrict__ b) {
    char* smem = dyn_smem;
    float* sBias = reinterpret_cast<float*>(smem + NODE_BIAS);
    const uint32_t sb0 = smem_u32(smem);
    const int tid = threadIdx.x, lane = tid & 31, w = tid >> 5;
    const int base = blockIdx.x * 128;

    if (tid < 128) sBias[tid] = b[tid];
    for (int i = tid; i < 128 * 32; i += 512) {
        int r = i >> 5, c = (i & 31) * 4;
        int gr = base + r;
        float4 v = make_float4(0.f, 0.f, 0.f, 0.f);
        if (gr < NN) v = *reinterpret_cast<const float4*>(nf + (size_t)gr * HID + c);
        __half2* p = reinterpret_cast<__half2*>(smem + NODE_SA + r * SA_STR + c * 2);
        p[0] = __floats2half2_rn(v.x, v.y);
        p[1] = __floats2half2_rn(v.z, v.w);
    }
    for (int i = tid; i < 128 * 16; i += 512) {
        int r = i >> 4, s = (i & 15);
        *reinterpret_cast<float4*>(smem + NODE_SB + r * SA_STR + s * 16) =
            *reinterpret_cast<const float4*>(
                reinterpret_cast<const char*>(g_nWt) + (size_t)r * 256 + s * 16);
    }
    __syncthreads();

    const int mb = (w & 3) * 32, nb = (w >> 2) * 32;
    uint32_t aA0 = sb0 + NODE_SA + (uint32_t)mb * SA_STR + a_off(lane, SA_STR);
    uint32_t aA1 = aA0 + 16 * SA_STR;
    uint32_t bA[2];
#pragma unroll
    for (int jj = 0; jj < 2; ++jj)
        bA[jj] = sb0 + NODE_SB + (uint32_t)(nb + jj * 16) * SA_STR + b_off(lane, SA_STR);

    float acc[2][4][4];
    zacc(acc);
    wgemm<8>(aA0, aA1, bA, acc);

    const int g = lane >> 2, tg = lane & 3;
#pragma unroll
    for (int i = 0; i < 2; ++i) {
        int r0 = base + mb + i * 16 + g;
#pragma unroll
        for (int j = 0; j < 4; ++j) {
            int c = nb + j * 8 + 2 * tg;
            if (r0 < NN)
                *reinterpret_cast<__half2*>(g_h + (size_t)r0 * HID + c) =
                    __floats2half2_rn(acc[i][j][0] + sBias[c], acc[i][j][1] + sBias[c + 1]);
            if (r0 + 8 < NN)
                *reinterpret_cast<__half2*>(g_h + (size_t)(r0 + 8) * HID + c) =
                    __floats2half2_rn(acc[i][j][2] + sBias[c], acc[i][j][3] + sBias[c + 1]);
        }
    }
}

// ---------------------------------------------------------------------------
// Kernel 2: fused edge pipeline, 5 tiles/CTA, weights resident,
// scatter via cp.reduce.async.bulk (TMA reduce) instead of scalar atomics.
// ---------------------------------------------------------------------------
static constexpr int SH_B  = 0;
static constexpr int SE_B  = 34816;
static constexpr int EF0_B = 69632;
static constexpr int EF1_B = 88064;
static constexpr int EW_B  = 106496;
static constexpr int W1_B  = 124928;
static constexpr int W2_B  = 192512;
static constexpr int MISC_B = 227328;
static constexpr int EDGE_SMEM = MISC_B + 1536;  // 228864

__global__ __launch_bounds__(512, 1) void k_edge(const int* __restrict__ eidx,
                                                 const float* __restrict__ ef,
                                                 const float* __restrict__ eb,
                                                 const float* __restrict__ b1,
                                                 const float* __restrict__ b2) {
    char* smem = dyn_smem;
    float* sEB = reinterpret_cast<float*>(smem + MISC_B);
    float* sB1b = sEB + 128;
    float* sB2b = sB1b + 128;
    const uint32_t sb0 = smem_u32(smem);

    const int tid = threadIdx.x, lane = tid & 31, w = tid >> 5;
    const int ebase = blockIdx.x * (T_TILES * 128);

    if (tid < 128) sEB[tid] = eb[tid];
    else if (tid < 256) {
        sB1b[tid - 128] = b1[tid - 128];
        sB2b[tid - 128] = b2[tid - 128];
    }

    // ---- prologue: weights + gather(0); ef(0) via LDG/STS ----
    stage_w<64>(sb0 + EW_B, EW_STR, g_eWt, 64, tid);
    stage_w<256>(sb0 + W1_B, W1_STR, g_W1t, 256, tid);
    stage_w<128>(sb0 + W2_B, W2_STR, g_W2t, 128, tid);
#pragma unroll
    for (int i = tid; i < 128 * 16; i += 512) {
        int r = i >> 4, s = i & 15;
        int src = eidx[ebase + r];
        CP16(sb0 + SH_B + (uint32_t)(r * SA_STR + s * 16),
             g_h + (size_t)src * HID + s * 8);
    }
    CP_COMMIT();
#pragma unroll
    for (int i = tid; i < 128 * 16; i += 512) {
        int r = i >> 4, c = (i & 15) * 4;
        float4 v = *reinterpret_cast<const float4*>(ef + (size_t)(ebase + r) * 64 + c);
        __half2* p = reinterpret_cast<__half2*>(smem + EF0_B + r * EF_STR + c * 2);
        p[0] = __floats2half2_rn(v.x, v.y);
        p[1] = __floats2half2_rn(v.z, v.w);
    }
    CP_WAIT(0);
    __syncthreads();

    const int mb = (w & 3) * 32, nb = (w >> 2) * 32;
    uint32_t aH0 = sb0 + SH_B + (uint32_t)mb * SA_STR + a_off(lane, SA_STR);
    uint32_t aH1 = aH0 + 16 * SA_STR;
    uint32_t aS0 = sb0 + SE_B + (uint32_t)mb * SA_STR + a_off(lane, SA_STR);
    uint32_t aS1 = aS0 + 16 * SA_STR;
    uint32_t aF0[2], aF1[2];
    aF0[0] = sb0 + EF0_B + (uint32_t)mb * EF_STR + a_off(lane, EF_STR);
    aF1[0] = aF0[0] + 16 * EF_STR;
    aF0[1] = aF0[0] + (EF1_B - EF0_B);
    aF1[1] = aF1[0] + (EF1_B - EF0_B);
    uint32_t bEW[2], bW1[2], bW2[2];
#pragma unroll
    for (int jj = 0; jj < 2; ++jj) {
        int nrow = nb + jj * 16;
        bEW[jj] = sb0 + EW_B + (uint32_t)nrow * EW_STR + b_off(lane, EW_STR);
        bW1[jj] = sb0 + W1_B + (uint32_t)nrow * W1_STR + b_off(lane, W1_STR);
        bW2[jj] = sb0 + W2_B + (uint32_t)nrow * W2_STR + b_off(lane, W2_STR);
    }

    const int g = lane >> 2, tg = lane & 3;
    float acc[2][4][4];

#pragma unroll 1
    for (int t = 0; t < T_TILES; ++t) {
        const int e0 = ebase + t * 128;
        const int cur = t & 1, nxt = cur ^ 1;
        const bool pf = (t + 1 < T_TILES);

        // ---- GEMM0: e = ef @ eWt (K=64), A = sEF[cur] ----
        zacc(acc);
        wgemm<4>(aF0[cur], aF1[cur], bEW, acc);

        // prefetch ef(t+1) into registers
        float4 efr[4];
        if (pf) {
#pragma unroll
            for (int j = 0; j < 4; ++j) {
                int idx = tid + j * 512;
                int r = idx >> 4, c = (idx & 15) * 4;
                efr[j] = *reinterpret_cast<const float4*>(
                    ef + (size_t)(e0 + 128 + r) * 64 + c);
            }
        }

        // epilogue0: e = acc + eb -> sE fp16 (sE free: bulk reads drained)
#pragma unroll
        for (int i = 0; i < 2; ++i) {
            int r0 = mb + i * 16 + g;
#pragma unroll
            for (int j = 0; j < 4; ++j) {
                int c = nb + j * 8 + 2 * tg;
                *reinterpret_cast<__half2*>(smem + SE_B + r0 * SA_STR + c * 2) =
                    __floats2half2_rn(acc[i][j][0] + sEB[c], acc[i][j][1] + sEB[c + 1]);
                *reinterpret_cast<__half2*>(smem + SE_B + (r0 + 8) * SA_STR + c * 2) =
                    __floats2half2_rn(acc[i][j][2] + sEB[c], acc[i][j][3] + sEB[c + 1]);
            }
        }
        if (pf) {
            uint32_t efb = (nxt ? EF1_B : EF0_B);
#pragma unroll
            for (int j = 0; j < 4; ++j) {
                int idx = tid + j * 512;
                int r = idx >> 4, c = (idx & 15) * 4;
                __half2* p = reinterpret_cast<__half2*>(smem + efb + r * EF_STR + c * 2);
                p[0] = __floats2half2_rn(efr[j].x, efr[j].y);
                p[1] = __floats2half2_rn(efr[j].z, efr[j].w);
            }
        }
        __syncthreads();  // publish e + ef STS

        // ---- GEMM1: t = [h|e] @ W1 (K=256) ----
        zacc(acc);
        wgemm<8>(aH0, aH1, bW1, acc);
        {
            uint32_t bW1hi[2] = {bW1[0] + 256, bW1[1] + 256};
            wgemm<8>(aS0, aS1, bW1hi, acc);
        }
        __syncthreads();  // sH + sE reads done

        // gather(t+1) -> sH ; epilogue1: t = relu(acc+b1) -> sE fp16
        if (pf) {
#pragma unroll
            for (int i = tid; i < 128 * 16; i += 512) {
                int r = i >> 4, s = i & 15;
                int src = eidx[e0 + 128 + r];
                CP16(sb0 + SH_B + (uint32_t)(r * SA_STR + s * 16),
                     g_h + (size_t)src * HID + s * 8);
            }
            CP_COMMIT();
        }
#pragma unroll
        for (int i = 0; i < 2; ++i) {
            int r0 = mb + i * 16 + g;
#pragma unroll
            for (int j = 0; j < 4; ++j) {
                int c = nb + j * 8 + 2 * tg;
                *reinterpret_cast<__half2*>(smem + SE_B + r0 * SA_STR + c * 2) =
                    __floats2half2_rn(fmaxf(acc[i][j][0] + sB1b[c], 0.f),
                                      fmaxf(acc[i][j][1] + sB1b[c + 1], 0.f));
                *reinterpret_cast<__half2*>(smem + SE_B + (r0 + 8) * SA_STR + c * 2) =
                    __floats2half2_rn(fmaxf(acc[i][j][2] + sB1b[c], 0.f),
                                      fmaxf(acc[i][j][3] + sB1b[c + 1], 0.f));
            }
        }
        __syncthreads();  // publish t

        // ---- GEMM2: m = t @ W2 (K=128), A = sE ----
        zacc(acc);
        wgemm<8>(aS0, aS1, bW2, acc);
        __syncthreads();  // sE reads done -> safe to stage m

        // ---- scatter via bulk reduce, two 64-col passes ----
        // pass A: cols [0,64)
        if (nb < 64) {
#pragma unroll
            for (int i = 0; i < 2; ++i) {
                int r0 = mb + i * 16 + g;
#pragma unroll
                for (int j = 0; j < 4; ++j) {
                    int c = nb + j * 8 + 2 * tg;
                    *reinterpret_cast<float2*>(smem + SE_B + r0 * SA_STR + c * 4) =
                        make_float2(acc[i][j][0] + sB2b[c], acc[i][j][1] + sB2b[c + 1]);
                    *reinterpret_cast<float2*>(smem + SE_B + (r0 + 8) * SA_STR + c * 4) =
                        make_float2(acc[i][j][2] + sB2b[c], acc[i][j][3] + sB2b[c + 1]);
                }
            }
        }
        __syncthreads();
        if (tid < 128) {
            FENCE_ASYNC();
            int d = eidx[NE + e0 + tid];
            BULK_RED_F32(g_agg + (size_t)d * HID,
                         sb0 + SE_B + (uint32_t)tid * SA_STR, 256);
            BULK_COMMIT();
            BULK_WAIT_RD0();
        }
        __syncthreads();  // sE readable for pass B

        // pass B: cols [64,128)
        if (nb >= 64) {
#pragma unroll
            for (int i = 0; i < 2; ++i) {
                int r0 = mb + i * 16 + g;
#pragma unroll
                for (int j = 0; j < 4; ++j) {
                    int c = nb + j * 8 + 2 * tg;
                    *reinterpret_cast<float2*>(smem + SE_B + r0 * SA_STR + (c - 64) * 4) =
                        make_float2(acc[i][j][0] + sB2b[c], acc[i][j][1] + sB2b[c + 1]);
                    *reinterpret_cast<float2*>(smem + SE_B + (r0 + 8) * SA_STR + (c - 64) * 4) =
                        make_float2(acc[i][j][2] + sB2b[c], acc[i][j][3] + sB2b[c + 1]);
                }
            }
        }
        __syncthreads();
        if (tid < 128) {
            FENCE_ASYNC();
            int d = eidx[NE + e0 + tid];
            BULK_RED_F32(g_agg + (size_t)d * HID + 64,
                         sb0 + SE_B + (uint32_t)tid * SA_STR, 256);
            BULK_COMMIT();
            BULK_WAIT_RD0();
        }
        CP_WAIT(0);       // gather(t+1) landed
        __syncthreads();  // sE reusable next tile; sH published
    }
    if (tid < 128) BULK_WAIT0();  // writes complete before kernel end
}

// ---------------------------------------------------------------------------
// Kernel 3: out = relu([nf|agg] @ U1 + ub1) @ U2 + ub2
// ---------------------------------------------------------------------------
static constexpr int UPD_SH = 0;
static constexpr int UPD_SE = 128 * SA_STR;
static constexpr int UPD_U1 = 2 * 128 * SA_STR;
static constexpr int UPD_U2 = UPD_U1 + 128 * W1_STR;
static constexpr int UPD_B1 = UPD_U2 + 128 * W2_STR;
static constexpr int UPD_B2 = UPD_B1 + 512;
static constexpr int UPD_SMEM = UPD_B2 + 512;

__global__ __launch_bounds__(512, 1) void k_update(const float* __restrict__ nf,
                                                   const float* __restrict__ b1,
                                                   const float* __restrict__ b2,
                                                   float* __restrict__ out) {
    char* smem = dyn_smem;
    float* sB1 = reinterpret_cast<float*>(smem + UPD_B1);
    float* sB2 = reinterpret_cast<float*>(smem + UPD_B2);
    const uint32_t sb0 = smem_u32(smem);

    const int tid = threadIdx.x, lane = tid & 31, w = tid >> 5;
    const int base = blockIdx.x * 128;

    if (tid < 128) {
        sB1[tid] = b1[tid];
        sB2[tid] = b2[tid];
    }
    stage_w<256>(sb0 + UPD_U1, W1_STR, g_U1t, 256, tid);
    stage_w<128>(sb0 + UPD_U2, W2_STR, g_U2t, 128, tid);
    CP_COMMIT();

    for (int i = tid; i < 128 * 32; i += 512) {
        int r = i >> 5, c = (i & 31) * 4;
        int gr = base + r;
        float4 v0 = make_float4(0.f, 0.f, 0.f, 0.f), v1 = v0;
        if (gr < NN) {
            v0 = *reinterpret_cast<const float4*>(nf + (size_t)gr * HID + c);
            v1 = *reinterpret_cast<const float4*>(g_agg + (size_t)gr * HID + c);
        }
        __half2* p0 = reinterpret_cast<__half2*>(smem + UPD_SH + r * SA_STR + c * 2);
        p0[0] = __floats2half2_rn(v0.x, v0.y);
        p0[1] = __floats2half2_rn(v0.z, v0.w);
        __half2* p1 = reinterpret_cast<__half2*>(smem + UPD_SE + r * SA_STR + c * 2);
        p1[0] = __floats2half2_rn(v1.x, v1.y);
        p1[1] = __floats2half2_rn(v1.z, v1.w);
    }
    CP_WAIT(0);
    __syncthreads();

    const int mb = (w & 3) * 32, nb = (w >> 2) * 32;
    uint32_t aH0 = sb0 + UPD_SH + (uint32_t)mb * SA_STR + a_off(lane, SA_STR);
    uint32_t aH1 = aH0 + 16 * SA_STR;
    uint32_t aE0 = sb0 + UPD_SE + (uint32_t)mb * SA_STR + a_off(lane, SA_STR);
    uint32_t aE1 = aE0 + 16 * SA_STR;
    uint32_t bU1[2], bU2[2];
#pragma unroll
    for (int jj = 0; jj < 2; ++jj) {
        int nrow = nb + jj * 16;
        bU1[jj] = sb0 + UPD_U1 + (uint32_t)nrow * W1_STR + b_off(lane, W1_STR);
        bU2[jj] = sb0 + UPD_U2 + (uint32_t)nrow * W2_STR + b_off(lane, W2_STR);
    }

    const int g = lane >> 2, tg = lane & 3;
    float acc[2][4][4];

    zacc(acc);
    wgemm<8>(aH0, aH1, bU1, acc);
    {
        uint32_t bU1hi[2] = {bU1[0] + 256, bU1[1] + 256};
        wgemm<8>(aE0, aE1, bU1hi, acc);
    }
    __syncthreads();
#pragma unroll
    for (int i = 0; i < 2; ++i) {
        int r0 = mb + i * 16 + g;
#pragma unroll
        for (int j = 0; j < 4; ++j) {
            int c = nb + j * 8 + 2 * tg;
            *reinterpret_cast<__half2*>(smem + UPD_SH + r0 * SA_STR + c * 2) =
                __floats2half2_rn(fmaxf(acc[i][j][0] + sB1[c], 0.f),
                                  fmaxf(acc[i][j][1] + sB1[c + 1], 0.f));
            *reinterpret_cast<__half2*>(smem + UPD_SH + (r0 + 8) * SA_STR + c * 2) =
                __floats2half2_rn(fmaxf(acc[i][j][2] + sB1[c], 0.f),
                                  fmaxf(acc[i][j][3] + sB1[c + 1], 0.f));
        }
    }
    __syncthreads();

    zacc(acc);
    wgemm<8>(aH0, aH1, bU2, acc);
#pragma unroll
    for (int i = 0; i < 2; ++i) {
        int r0 = base + mb + i * 16 + g;
#pragma unroll
        for (int j = 0; j < 4; ++j) {
            int c = nb + j * 8 + 2 * tg;
            if (r0 < NN)
                *reinterpret_cast<float2*>(out + (size_t)r0 * HID + c) =
                    make_float2(acc[i][j][0] + sB2[c], acc[i][j][1] + sB2[c + 1]);
            if (r0 + 8 < NN)
                *reinterpret_cast<float2*>(out + (size_t)(r0 + 8) * HID + c) =
                    make_float2(acc[i][j][2] + sB2[c], acc[i][j][3] + sB2[c + 1]);
        }
    }
}

// ---------------------------------------------------------------------------
extern "C" void kernel_launch(void* const* d_in, const int* in_sizes, int n_in,
                              void* d_out, int out_size) {
    const float* node_feats = (const float*)d_in[0];
    const int*   edge_idx   = (const int*)d_in[1];
    const float* edge_feats = (const float*)d_in[2];
    const float* node_W     = (const float*)d_in[3];
    const float* node_b     = (const float*)d_in[4];
    const float* edge_W     = (const float*)d_in[5];
    const float* edge_b     = (const float*)d_in[6];
    const float* msg_W1     = (const float*)d_in[7];
    const float* msg_b1     = (const float*)d_in[8];
    const float* msg_W2     = (const float*)d_in[9];
    const float* msg_b2     = (const float*)d_in[10];
    const float* upd_W1     = (const float*)d_in[11];
    const float* upd_b1     = (const float*)d_in[12];
    const float* upd_W2     = (const float*)d_in[13];
    const float* upd_b2     = (const float*)d_in[14];
    float* out = (float*)d_out;

    cudaFuncSetAttribute(k_node,   cudaFuncAttributeMaxDynamicSharedMemorySize, NODE_SMEM);
    cudaFuncSetAttribute(k_edge,   cudaFuncAttributeMaxDynamicSharedMemorySize, EDGE_SMEM);
    cudaFuncSetAttribute(k_update, cudaFuncAttributeMaxDynamicSharedMemorySize, UPD_SMEM);

    const int NB_NODE = (NN + 127) / 128;      // 391
    const int NB_EDGE = NE / (128 * T_TILES);  // 1250

    k_tW<<<128, 256>>>(node_W, edge_W, msg_W1, msg_W2, upd_W1, upd_W2);
    k_zero_agg<<<NN * HID / 4 / 256, 256>>>();
    k_node<<<NB_NODE, 512, NODE_SMEM>>>(node_feats, node_b);
    k_edge<<<NB_EDGE, 512, EDGE_SMEM>>>(edge_idx, edge_feats, edge_b, msg_b1, msg_b2);
    k_update<<<NB_NODE, 512, UPD_SMEM>>>(node_feats, upd_b1, upd_b2, out);
}

// round 13
// speedup vs baseline: 1.2892x; 1.2892x over previous
#include <cuda_runtime.h>
#include <cuda_fp16.h>
#include <cstdint>

#define HID 128
#define NN 50000
#define NE 800000
// byte strides (all ≡16 mod 128 -> ldmatrix conflict-free)
#define SA_STR 272   // A tiles rows: 136 halves
#define SB_STR 144   // B K=64 chunk buffers rows: 72 halves
#define W1_STR 528
#define W2_STR 272

extern __shared__ char dyn_smem[];

// ---------------- device scratch (allocation-free rule) ----------------
__device__ __half g_h[(size_t)NN * HID];
__device__ float  g_agg[(size_t)NN * HID];
__device__ __half g_nWt[128 * 128];
__device__ __half g_eWt[128 * 64];
__device__ __half g_W1t[128 * 256];
__device__ __half g_W2t[128 * 128];
__device__ __half g_U1t[128 * 256];
__device__ __half g_U2t[128 * 128];

// ======================= helpers (generic PTX) =========================
__device__ __forceinline__ uint32_t smem_u32(const void* p) {
    uint32_t a;
    asm("{ .reg .u64 t; cvta.to.shared.u64 t, %1; cvt.u32.u64 %0, t; }"
        : "=r"(a) : "l"(p));
    return a;
}
__device__ __forceinline__ void ldsm4(uint32_t r[4], uint32_t addr) {
    asm volatile("ldmatrix.sync.aligned.m8n8.x4.shared.b16 {%0,%1,%2,%3}, [%4];"
                 : "=r"(r[0]), "=r"(r[1]), "=r"(r[2]), "=r"(r[3]) : "r"(addr));
}
__device__ __forceinline__ void mma16(float c[4], const uint32_t a[4],
                                      uint32_t b0, uint32_t b1) {
    asm volatile("mma.sync.aligned.m16n8k16.row.col.f32.f16.f16.f32 "
                 "{%0,%1,%2,%3}, {%4,%5,%6,%7}, {%8,%9}, {%0,%1,%2,%3};"
                 : "+f"(c[0]), "+f"(c[1]), "+f"(c[2]), "+f"(c[3])
                 : "r"(a[0]), "r"(a[1]), "r"(a[2]), "r"(a[3]), "r"(b0), "r"(b1));
}
#define CP16(dst, src) \
    asm volatile("cp.async.cg.shared.global [%0], [%1], 16;" :: "r"(dst), "l"(src))
#define CP_COMMIT() asm volatile("cp.async.commit_group;" ::: "memory")
#define CP_WAIT(n)  asm volatile("cp.async.wait_group %0;" :: "n"(n) : "memory")

__device__ __forceinline__ uint32_t a_off(int lane, int strideB) {
    int row = (lane & 7) + ((lane & 8) ? 8 : 0);
    return (uint32_t)row * strideB + ((lane & 16) ? 16 : 0);
}
__device__ __forceinline__ uint32_t b_off(int lane, int strideB) {
    int row = (lane & 7) + ((lane & 16) ? 8 : 0);
    return (uint32_t)row * strideB + ((lane & 8) ? 16 : 0);
}

// ---- 64x32 warp GEMM (4 m16-tiles x 4 n8-cols), KSTEPS k-steps of 16 ----
__device__ __forceinline__ void zacc64(float acc[4][4][4]) {
#pragma unroll
    for (int m = 0; m < 4; ++m)
#pragma unroll
        for (int j = 0; j < 4; ++j)
#pragma unroll
            for (int k = 0; k < 4; ++k) acc[m][j][k] = 0.f;
}
template <int KSTEPS>
__device__ __forceinline__ void wgemm64(const uint32_t aA[4], const uint32_t bA[2],
                                        float acc[4][4][4]) {
#pragma unroll
    for (int ks = 0; ks < KSTEPS; ++ks) {
        uint32_t b0[4], b1[4];
        ldsm4(b0, bA[0] + ks * 32);
        ldsm4(b1, bA[1] + ks * 32);
#pragma unroll
        for (int m = 0; m < 4; ++m) {
            uint32_t a[4];
            ldsm4(a, aA[m] + ks * 32);
            mma16(acc[m][0], a, b0[0], b0[1]);
            mma16(acc[m][1], a, b0[2], b0[3]);
            mma16(acc[m][2], a, b1[0], b1[1]);
            mma16(acc[m][3], a, b1[2], b1[3]);
        }
    }
}

// ---- 32x32 warp GEMM (R9 form, used by k_node / k_update @512 thr) ----
__device__ __forceinline__ void zacc(float acc[2][4][4]) {
#pragma unroll
    for (int i = 0; i < 2; ++i)
#pragma unroll
        for (int j = 0; j < 4; ++j)
#pragma unroll
            for (int k = 0; k < 4; ++k) acc[i][j][k] = 0.f;
}
template <int KSTEPS>
__device__ __forceinline__ void wgemm(uint32_t aA0, uint32_t aA1,
                                      const uint32_t bA[2], float acc[2][4][4]) {
#pragma unroll
    for (int ks = 0; ks < KSTEPS; ++ks) {
        uint32_t a0[4], a1[4];
        ldsm4(a0, aA0 + ks * 32);
        ldsm4(a1, aA1 + ks * 32);
#pragma unroll
        for (int jj = 0; jj < 2; ++jj) {
            uint32_t b[4];
            ldsm4(b, bA[jj] + ks * 32);
            mma16(acc[0][2 * jj],     a0, b[0], b[1]);
            mma16(acc[0][2 * jj + 1], a0, b[2], b[3]);
            mma16(acc[1][2 * jj],     a1, b[0], b[1]);
            mma16(acc[1][2 * jj + 1], a1, b[2], b[3]);
        }
    }
}

// cp.async [128n x 64k] fp16 weight chunk into SB_STR buffer (256 threads)
__device__ __forceinline__ void stage_chunk256(uint32_t dstB, const __half* srcBase,
                                               int srcK, int tid) {
#pragma unroll
    for (int i = tid; i < 128 * 8; i += 256) {
        int n = i >> 3, k8 = (i & 7) * 8;
        CP16(dstB + (uint32_t)(n * SB_STR + k8 * 2),
             srcBase + (size_t)n * srcK + k8);
    }
}
// cp.async weight tile with arbitrary dst stride (512 threads, for k_update)
template <int KH>
__device__ __forceinline__ void stage_w(uint32_t dstB, int dstStr,
                                        const __half* srcBase, int srcK, int tid) {
    constexpr int SEGS = KH / 8;
#pragma unroll
    for (int i = tid; i < 128 * SEGS; i += 512) {
        int n = i / SEGS, s = i % SEGS;
        CP16(dstB + (uint32_t)(n * dstStr + s * 16),
             srcBase + (size_t)n * srcK + s * 8);
    }
}

// ---------------------------------------------------------------------------
__global__ void k_tW(const float* __restrict__ nW, const float* __restrict__ eW,
                     const float* __restrict__ W1, const float* __restrict__ W2,
                     const float* __restrict__ U1, const float* __restrict__ U2) {
    int t = blockIdx.x * blockDim.x + threadIdx.x;
    int tot = gridDim.x * blockDim.x;
    for (int i = t; i < 128 * 128; i += tot) {
        int n = i >> 7, k = i & 127;
        g_nWt[i] = __float2half_rn(nW[k * 128 + n]);
        g_W2t[i] = __float2half_rn(W2[k * 128 + n]);
        g_U2t[i] = __float2half_rn(U2[k * 128 + n]);
    }
    for (int i = t; i < 128 * 64; i += tot) {
        int n = i >> 6, k = i & 63;
        g_eWt[i] = __float2half_rn(eW[k * 128 + n]);
    }
    for (int i = t; i < 128 * 256; i += tot) {
        int n = i >> 8, k = i & 255;
        g_W1t[i] = __float2half_rn(W1[k * 128 + n]);
        g_U1t[i] = __float2half_rn(U1[k * 128 + n]);
    }
}

__global__ __launch_bounds__(256) void k_zero_agg() {
    size_t i = (size_t)blockIdx.x * 256 + threadIdx.x;
    reinterpret_cast<float4*>(g_agg)[i] = make_float4(0.f, 0.f, 0.f, 0.f);
}

// ---------------------------------------------------------------------------
// Kernel 1: h = fp16(node_feats @ node_W + node_b) -> g_h   (512 thr)
// ---------------------------------------------------------------------------
static constexpr int NODE_SA = 0;
static constexpr int NODE_SB = 128 * SA_STR;
static constexpr int NODE_BIAS = NODE_SB + 128 * SA_STR;
static constexpr int NODE_SMEM = NODE_BIAS + 512;

__global__ __launch_bounds__(512, 1) void k_node(const float* __restrict__ nf,
                                                 const float* __restrict__ b) {
    char* smem = dyn_smem;
    float* sBias = reinterpret_cast<float*>(smem + NODE_BIAS);
    const uint32_t sb0 = smem_u32(smem);
    const int tid = threadIdx.x, lane = tid & 31, w = tid >> 5;
    const int base = blockIdx.x * 128;

    if (tid < 128) sBias[tid] = b[tid];
    for (int i = tid; i < 128 * 32; i += 512) {
        int r = i >> 5, c = (i & 31) * 4;
        int gr = base + r;
        float4 v = make_float4(0.f, 0.f, 0.f, 0.f);
        if (gr < NN) v = *reinterpret_cast<const float4*>(nf + (size_t)gr * HID + c);
        __half2* p = reinterpret_cast<__half2*>(smem + NODE_SA + r * SA_STR + c * 2);
        p[0] = __floats2half2_rn(v.x, v.y);
        p[1] = __floats2half2_rn(v.z, v.w);
    }
    for (int i = tid; i < 128 * 16; i += 512) {
        int r = i >> 4, s = (i & 15);
        *reinterpret_cast<float4*>(smem + NODE_SB + r * SA_STR + s * 16) =
            *reinterpret_cast<const float4*>(
                reinterpret_cast<const char*>(g_nWt) + (size_t)r * 256 + s * 16);
    }
    __syncthreads();

    const int mb = (w & 3) * 32, nb = (w >> 2) * 32;
    uint32_t aA0 = sb0 + NODE_SA + (uint32_t)mb * SA_STR + a_off(lane, SA_STR);
    uint32_t aA1 = aA0 + 16 * SA_STR;
    uint32_t bA[2];
#pragma unroll
    for (int jj = 0; jj < 2; ++jj)
        bA[jj] = sb0 + NODE_SB + (uint32_t)(nb + jj * 16) * SA_STR + b_off(lane, SA_STR);

    float acc[2][4][4];
    zacc(acc);
    wgemm<8>(aA0, aA1, bA, acc);

    const int g = lane >> 2, tg = lane & 3;
#pragma unroll
    for (int i = 0; i < 2; ++i) {
        int r0 = base + mb + i * 16 + g;
#pragma unroll
        for (int j = 0; j < 4; ++j) {
            int c = nb + j * 8 + 2 * tg;
            if (r0 < NN)
                *reinterpret_cast<__half2*>(g_h + (size_t)r0 * HID + c) =
                    __floats2half2_rn(acc[i][j][0] + sBias[c], acc[i][j][1] + sBias[c + 1]);
            if (r0 + 8 < NN)
                *reinterpret_cast<__half2*>(g_h + (size_t)(r0 + 8) * HID + c) =
                    __floats2half2_rn(acc[i][j][2] + sBias[c], acc[i][j][3] + sBias[c + 1]);
        }
    }
}

// ---------------------------------------------------------------------------
// Kernel 2: fused edge pipeline — 256 threads, 2 CTAs/SM, 64x32 warp tiles,
// R9-style double-buffered K=64 weight chunks, scalar-atomic scatter.
// smem: sH | sE | B0 | B1 | misc  (108544 B -> 2 CTAs/SM)
// ---------------------------------------------------------------------------
static constexpr int SH_B  = 0;
static constexpr int SE_B  = 128 * SA_STR;             // 34816
static constexpr int B0_B  = SE_B * 2;                 // 69632
static constexpr int B1_B  = B0_B + 128 * SB_STR;      // 88064
static constexpr int MISC_B = B1_B + 128 * SB_STR;     // 106496
static constexpr int EDGE_SMEM = MISC_B + 4 * 128 * 4; // 108544

__global__ __launch_bounds__(256, 2) void k_edge(const int* __restrict__ eidx,
                                                 const float* __restrict__ ef,
                                                 const float* __restrict__ eb,
                                                 const float* __restrict__ b1,
                                                 const float* __restrict__ b2) {
    char* smem = dyn_smem;
    float* sEB = reinterpret_cast<float*>(smem + MISC_B);
    float* sB1b = sEB + 128;
    float* sB2b = sB1b + 128;
    int* sDst = reinterpret_cast<int*>(sB2b + 128);
    const uint32_t sb0 = smem_u32(smem);

    const int tid = threadIdx.x, lane = tid & 31, w = tid >> 5;
    const int e0 = blockIdx.x * 128;

    if (tid < 128) {
        sDst[tid] = eidx[NE + e0 + tid];
        sEB[tid] = eb[tid];
    } else {
        sB1b[tid - 128] = b1[tid - 128];
        sB2b[tid - 128] = b2[tid - 128];
    }

    // group0: c0 = eWt -> B0
    stage_chunk256(sb0 + B0_B, g_eWt, 64, tid);
    CP_COMMIT();
    // group1: gather h[src] (fp16) -> sH
#pragma unroll
    for (int i = tid; i < 128 * 16; i += 256) {
        int r = i >> 4, s = i & 15;
        int src = eidx[e0 + r];
        CP16(sb0 + SH_B + (uint32_t)(r * SA_STR + s * 16),
             g_h + (size_t)src * HID + s * 8);
    }
    CP_COMMIT();
    // group2: c1 = W1t[:,0:64] -> B1
    stage_chunk256(sb0 + B1_B, g_W1t, 256, tid);
    CP_COMMIT();

    // ef [128x64] fp32 -> fp16 into sE cols 0..63
#pragma unroll
    for (int i = tid; i < 128 * 16; i += 256) {
        int r = i >> 4, c = (i & 15) * 4;
        float4 v = *reinterpret_cast<const float4*>(ef + (size_t)(e0 + r) * 64 + c);
        __half2* p = reinterpret_cast<__half2*>(smem + SE_B + r * SA_STR + c * 2);
        p[0] = __floats2half2_rn(v.x, v.y);
        p[1] = __floats2half2_rn(v.z, v.w);
    }

    // warp tiling: 2 (M) x 4 (N) warps, 64x32 each
    const int mb = (w & 1) * 64, nb = (w >> 1) * 32;
    uint32_t aH[4], aS[4];
#pragma unroll
    for (int m = 0; m < 4; ++m) {
        aH[m] = sb0 + SH_B + (uint32_t)(mb + m * 16) * SA_STR + a_off(lane, SA_STR);
        aS[m] = sb0 + SE_B + (uint32_t)(mb + m * 16) * SA_STR + a_off(lane, SA_STR);
    }
    uint32_t b0A[2], b1A[2];
#pragma unroll
    for (int jj = 0; jj < 2; ++jj) {
        uint32_t off = (uint32_t)(nb + jj * 16) * SB_STR + b_off(lane, SB_STR);
        b0A[jj] = sb0 + B0_B + off;
        b1A[jj] = sb0 + B1_B + off;
    }

    const int g = lane >> 2, tg = lane & 3;
    float acc[4][4][4];

    // ---- GEMM0: e = ef @ eWt (K=64, c0 in B0) ----
    CP_WAIT(2);
    __syncthreads();     // publish c0 + ef + biases
    zacc64(acc);
    wgemm64<4>(aS, b0A, acc);

    CP_WAIT(0);
    __syncthreads();     // publish sH, c1; B0 + sE(ef) free
    stage_chunk256(sb0 + B0_B, g_W1t + 64, 256, tid);  // c2 -> B0
    CP_COMMIT();

    // epilogue0: e = acc + eb -> sE
#pragma unroll
    for (int m = 0; m < 4; ++m) {
        int r0 = mb + m * 16 + g;
#pragma unroll
        for (int j = 0; j < 4; ++j) {
            int c = nb + j * 8 + 2 * tg;
            *reinterpret_cast<__half2*>(smem + SE_B + r0 * SA_STR + c * 2) =
                __floats2half2_rn(acc[m][j][0] + sEB[c], acc[m][j][1] + sEB[c + 1]);
            *reinterpret_cast<__half2*>(smem + SE_B + (r0 + 8) * SA_STR + c * 2) =
                __floats2half2_rn(acc[m][j][2] + sEB[c], acc[m][j][3] + sEB[c + 1]);
        }
    }

    // ---- GEMM1: t = relu([h|e] @ W1t + b1), 4 K=64 chunks ----
    zacc64(acc);
    wgemm64<4>(aH, b1A, acc);                      // c1: h k0:64
    CP_WAIT(0);
    __syncthreads();                               // publish c2 + epilogue0; B1 free
    stage_chunk256(sb0 + B1_B, g_W1t + 128, 256, tid);  // c3 -> B1
    CP_COMMIT();
    {
        uint32_t aH2[4] = {aH[0] + 128, aH[1] + 128, aH[2] + 128, aH[3] + 128};
        wgemm64<4>(aH2, b0A, acc);                 // c2: h k64:128
    }
    CP_WAIT(0);
    __syncthreads();                               // publish c3; B0 free
    stage_chunk256(sb0 + B0_B, g_W1t + 192, 256, tid);  // c4 -> B0
    CP_COMMIT();
    wgemm64<4>(aS, b1A, acc);                      // c3: e k0:64
    CP_WAIT(0);
    __syncthreads();                               // publish c4; B1 free
    stage_chunk256(sb0 + B1_B, g_W2t, 128, tid);   // c5 -> B1
    CP_COMMIT();
    {
        uint32_t aS2[4] = {aS[0] + 128, aS[1] + 128, aS[2] + 128, aS[3] + 128};
        wgemm64<4>(aS2, b0A, acc);                 // c4: e k64:128
    }
    CP_WAIT(0);
    __syncthreads();                               // publish c5; B0 free
    stage_chunk256(sb0 + B0_B, g_W2t + 64, 128, tid);  // c6 -> B0
    CP_COMMIT();

    // epilogue1: t = relu(acc + b1) -> sH (sH reads finished at c2)
#pragma unroll
    for (int m = 0; m < 4; ++m) {
        int r0 = mb + m * 16 + g;
#pragma unroll
        for (int j = 0; j < 4; ++j) {
            int c = nb + j * 8 + 2 * tg;
            *reinterpret_cast<__half2*>(smem + SH_B + r0 * SA_STR + c * 2) =
                __floats2half2_rn(fmaxf(acc[m][j][0] + sB1b[c], 0.f),
                                  fmaxf(acc[m][j][1] + sB1b[c + 1], 0.f));
            *reinterpret_cast<__half2*>(smem + SH_B + (r0 + 8) * SA_STR + c * 2) =
                __floats2half2_rn(fmaxf(acc[m][j][2] + sB1b[c], 0.f),
                                  fmaxf(acc[m][j][3] + sB1b[c + 1], 0.f));
        }
    }
    __syncthreads();                               // publish t

    // ---- GEMM2: m = t @ W2t + b2 (K=128) ----
    zacc64(acc);
    wgemm64<4>(aH, b1A, acc);                      // c5: t k0:64
    CP_WAIT(0);
    __syncthreads();                               // publish c6
    {
        uint32_t aH2[4] = {aH[0] + 128, aH[1] + 128, aH[2] + 128, aH[3] + 128};
        wgemm64<4>(aH2, b0A, acc);                 // c6: t k64:128
    }

    // scalar-atomic scatter into g_agg[dst]
#pragma unroll
    for (int m = 0; m < 4; ++m) {
        int r0 = mb + m * 16 + g;
        float* p0 = g_agg + (size_t)sDst[r0] * HID;
        float* p1 = g_agg + (size_t)sDst[r0 + 8] * HID;
#pragma unroll
        for (int j = 0; j < 4; ++j) {
            int c = nb + j * 8 + 2 * tg;
            atomicAdd(p0 + c, acc[m][j][0] + sB2b[c]);
            atomicAdd(p0 + c + 1, acc[m][j][1] + sB2b[c + 1]);
            atomicAdd(p1 + c, acc[m][j][2] + sB2b[c]);
            atomicAdd(p1 + c + 1, acc[m][j][3] + sB2b[c + 1]);
        }
    }
}

// ---------------------------------------------------------------------------
// Kernel 3: out = relu([nf|agg] @ U1 + ub1) @ U2 + ub2   (512 thr)
// ---------------------------------------------------------------------------
static constexpr int UPD_SH = 0;
static constexpr int UPD_SE = 128 * SA_STR;
static constexpr int UPD_U1 = 2 * 128 * SA_STR;
static constexpr int UPD_U2 = UPD_U1 + 128 * W1_STR;
static constexpr int UPD_B1 = UPD_U2 + 128 * W2_STR;
static constexpr int UPD_B2 = UPD_B1 + 512;
static constexpr int UPD_SMEM = UPD_B2 + 512;

__global__ __launch_bounds__(512, 1) void k_update(const float* __restrict__ nf,
                                                   const float* __restrict__ b1,
                                                   const float* __restrict__ b2,
                                                   float* __restrict__ out) {
    char* smem = dyn_smem;
    float* sB1 = reinterpret_cast<float*>(smem + UPD_B1);
    float* sB2 = reinterpret_cast<float*>(smem + UPD_B2);
    const uint32_t sb0 = smem_u32(smem);

    const int tid = threadIdx.x, lane = tid & 31, w = tid >> 5;
    const int base = blockIdx.x * 128;

    if (tid < 128) {
        sB1[tid] = b1[tid];
        sB2[tid] = b2[tid];
    }
    stage_w<256>(sb0 + UPD_U1, W1_STR, g_U1t, 256, tid);
    stage_w<128>(sb0 + UPD_U2, W2_STR, g_U2t, 128, tid);
    CP_COMMIT();

    for (int i = tid; i < 128 * 32; i += 512) {
        int r = i >> 5, c = (i & 31) * 4;
        int gr = base + r;
        float4 v0 = make_float4(0.f, 0.f, 0.f, 0.f), v1 = v0;
        if (gr < NN) {
            v0 = *reinterpret_cast<const float4*>(nf + (size_t)gr * HID + c);
            v1 = *reinterpret_cast<const float4*>(g_agg + (size_t)gr * HID + c);
        }
        __half2* p0 = reinterpret_cast<__half2*>(smem + UPD_SH + r * SA_STR + c * 2);
        p0[0] = __floats2half2_rn(v0.x, v0.y);
        p0[1] = __floats2half2_rn(v0.z, v0.w);
        __half2* p1 = reinterpret_cast<__half2*>(smem + UPD_SE + r * SA_STR + c * 2);
        p1[0] = __floats2half2_rn(v1.x, v1.y);
        p1[1] = __floats2half2_rn(v1.z, v1.w);
    }
    CP_WAIT(0);
    __syncthreads();

    const int mb = (w & 3) * 32, nb = (w >> 2) * 32;
    uint32_t aH0 = sb0 + UPD_SH + (uint32_t)mb * SA_STR + a_off(lane, SA_STR);
    uint32_t aH1 = aH0 + 16 * SA_STR;
    uint32_t aE0 = sb0 + UPD_SE + (uint32_t)mb * SA_STR + a_off(lane, SA_STR);
    uint32_t aE1 = aE0 + 16 * SA_STR;
    uint32_t bU1[2], bU2[2];
#pragma unroll
    for (int jj = 0; jj < 2; ++jj) {
        int nrow = nb + jj * 16;
        bU1[jj] = sb0 + UPD_U1 + (uint32_t)nrow * W1_STR + b_off(lane, W1_STR);
        bU2[jj] = sb0 + UPD_U2 + (uint32_t)nrow * W2_STR + b_off(lane, W2_STR);
    }

    const int g = lane >> 2, tg = lane & 3;
    float acc[2][4][4];

    zacc(acc);
    wgemm<8>(aH0, aH1, bU1, acc);
    {
        uint32_t bU1hi[2] = {bU1[0] + 256, bU1[1] + 256};
        wgemm<8>(aE0, aE1, bU1hi, acc);
    }
    __syncthreads();
#pragma unroll
    for (int i = 0; i < 2; ++i) {
        int r0 = mb + i * 16 + g;
#pragma unroll
        for (int j = 0; j < 4; ++j) {
            int c = nb + j * 8 + 2 * tg;
            *reinterpret_cast<__half2*>(smem + UPD_SH + r0 * SA_STR + c * 2) =
                __floats2half2_rn(fmaxf(acc[i][j][0] + sB1[c], 0.f),
                                  fmaxf(acc[i][j][1] + sB1[c + 1], 0.f));
            *reinterpret_cast<__half2*>(smem + UPD_SH + (r0 + 8) * SA_STR + c * 2) =
                __floats2half2_rn(fmaxf(acc[i][j][2] + sB1[c], 0.f),
                                  fmaxf(acc[i][j][3] + sB1[c + 1], 0.f));
        }
    }
    __syncthreads();

    zacc(acc);
    wgemm<8>(aH0, aH1, bU2, acc);
#pragma unroll
    for (int i = 0; i < 2; ++i) {
        int r0 = base + mb + i * 16 + g;
#pragma unroll
        for (int j = 0; j < 4; ++j) {
            int c = nb + j * 8 + 2 * tg;
            if (r0 < NN)
                *reinterpret_cast<float2*>(out + (size_t)r0 * HID + c) =
                    make_float2(acc[i][j][0] + sB2[c], acc[i][j][1] + sB2[c + 1]);
            if (r0 + 8 < NN)
                *reinterpret_cast<float2*>(out + (size_t)(r0 + 8) * HID + c) =
                    make_float2(acc[i][j][2] + sB2[c], acc[i][j][3] + sB2[c + 1]);
        }
    }
}

// ---------------------------------------------------------------------------
extern "C" void kernel_launch(void* const* d_in, const int* in_sizes, int n_in,
                              void* d_out, int out_size) {
    const float* node_feats = (const float*)d_in[0];
    const int*   edge_idx   = (const int*)d_in[1];
    const float* edge_feats = (const float*)d_in[2];
    const float* node_W     = (const float*)d_in[3];
    const float* node_b     = (const float*)d_in[4];
    const float* edge_W     = (const float*)d_in[5];
    const float* edge_b     = (const float*)d_in[6];
    const float* msg_W1     = (const float*)d_in[7];
    const float* msg_b1     = (const float*)d_in[8];
    const float* msg_W2     = (const float*)d_in[9];
    const float* msg_b2     = (const float*)d_in[10];
    const float* upd_W1     = (const float*)d_in[11];
    const float* upd_b1     = (const float*)d_in[12];
    const float* upd_W2     = (const float*)d_in[13];
    const float* upd_b2     = (const float*)d_in[14];
    float* out = (float*)d_out;

    cudaFuncSetAttribute(k_node,   cudaFuncAttributeMaxDynamicSharedMemorySize, NODE_SMEM);
    cudaFuncSetAttribute(k_edge,   cudaFuncAttributeMaxDynamicSharedMemorySize, EDGE_SMEM);
    cudaFuncSetAttribute(k_update, cudaFuncAttributeMaxDynamicSharedMemorySize, UPD_SMEM);

    const int NB_NODE = (NN + 127) / 128;  // 391
    const int NB_EDGE = NE / 128;          // 6250

    k_tW<<<128, 256>>>(node_W, edge_W, msg_W1, msg_W2, upd_W1, upd_W2);
    k_zero_agg<<<NN * HID / 4 / 256, 256>>>();
    k_node<<<NB_NODE, 512, NODE_SMEM>>>(node_feats, node_b);
    k_edge<<<NB_EDGE, 256, EDGE_SMEM>>>(edge_idx, edge_feats, edge_b, msg_b1, msg_b2);
    k_update<<<NB_NODE, 512, UPD_SMEM>>>(node_feats, upd_b1, upd_b2, out);
}

// round 14
// speedup vs baseline: 1.4146x; 1.0973x over previous
#include <cuda_runtime.h>
#include <cuda_fp16.h>
#include <cstdint>

#define HID 128
#define NN 50000
#define NE 800000
// byte strides (all ≡16 mod 128 -> ldmatrix conflict-free)
#define SA_STR 272   // A tiles rows: 136 halves
#define EF_STR 144   // ef tile rows: 72 halves
#define SB_STR 144   // B K=64 chunk buffers
#define W1_STR 528
#define W2_STR 272

extern __shared__ char dyn_smem[];

// ---------------- device scratch (allocation-free rule) ----------------
__device__ __half g_h[(size_t)NN * HID];
__device__ float  g_agg[(size_t)NN * HID];
__device__ __half g_nWt[128 * 128];
__device__ __half g_W1t[128 * 256];   // msg_W1^T [n][k]
__device__ __half g_W1et[128 * 64];   // (eW @ W1b)^T [n][kf]  (fused)
__device__ float  g_b1p[128];         // b1 + eb @ W1b
__device__ __half g_W2t[128 * 128];
__device__ __half g_U1t[128 * 256];
__device__ __half g_U2t[128 * 128];

// ======================= helpers (generic PTX) =========================
__device__ __forceinline__ uint32_t smem_u32(const void* p) {
    uint32_t a;
    asm("{ .reg .u64 t; cvta.to.shared.u64 t, %1; cvt.u32.u64 %0, t; }"
        : "=r"(a) : "l"(p));
    return a;
}
__device__ __forceinline__ void ldsm4(uint32_t r[4], uint32_t addr) {
    asm volatile("ldmatrix.sync.aligned.m8n8.x4.shared.b16 {%0,%1,%2,%3}, [%4];"
                 : "=r"(r[0]), "=r"(r[1]), "=r"(r[2]), "=r"(r[3]) : "r"(addr));
}
__device__ __forceinline__ void mma16(float c[4], const uint32_t a[4],
                                      uint32_t b0, uint32_t b1) {
    asm volatile("mma.sync.aligned.m16n8k16.row.col.f32.f16.f16.f32 "
                 "{%0,%1,%2,%3}, {%4,%5,%6,%7}, {%8,%9}, {%0,%1,%2,%3};"
                 : "+f"(c[0]), "+f"(c[1]), "+f"(c[2]), "+f"(c[3])
                 : "r"(a[0]), "r"(a[1]), "r"(a[2]), "r"(a[3]), "r"(b0), "r"(b1));
}
#define CP16(dst, src) \
    asm volatile("cp.async.cg.shared.global [%0], [%1], 16;" :: "r"(dst), "l"(src))
#define CP_COMMIT() asm volatile("cp.async.commit_group;" ::: "memory")
#define CP_WAIT(n)  asm volatile("cp.async.wait_group %0;" :: "n"(n) : "memory")

__device__ __forceinline__ uint32_t a_off(int lane, int strideB) {
    int row = (lane & 7) + ((lane & 8) ? 8 : 0);
    return (uint32_t)row * strideB + ((lane & 16) ? 16 : 0);
}
__device__ __forceinline__ uint32_t b_off(int lane, int strideB) {
    int row = (lane & 7) + ((lane & 16) ? 8 : 0);
    return (uint32_t)row * strideB + ((lane & 8) ? 16 : 0);
}

// ---- 64x32 warp GEMM (4 m16-tiles x 4 n8-cols) ----
__device__ __forceinline__ void zacc64(float acc[4][4][4]) {
#pragma unroll
    for (int m = 0; m < 4; ++m)
#pragma unroll
        for (int j = 0; j < 4; ++j)
#pragma unroll
            for (int k = 0; k < 4; ++k) acc[m][j][k] = 0.f;
}
template <int KSTEPS>
__device__ __forceinline__ void wgemm64(const uint32_t aA[4], const uint32_t bA[2],
                                        float acc[4][4][4]) {
#pragma unroll
    for (int ks = 0; ks < KSTEPS; ++ks) {
        uint32_t b0[4], b1[4];
        ldsm4(b0, bA[0] + ks * 32);
        ldsm4(b1, bA[1] + ks * 32);
#pragma unroll
        for (int m = 0; m < 4; ++m) {
            uint32_t a[4];
            ldsm4(a, aA[m] + ks * 32);
            mma16(acc[m][0], a, b0[0], b0[1]);
            mma16(acc[m][1], a, b0[2], b0[3]);
            mma16(acc[m][2], a, b1[0], b1[1]);
            mma16(acc[m][3], a, b1[2], b1[3]);
        }
    }
}

// ---- 32x32 warp GEMM (k_node / k_update @512 thr) ----
__device__ __forceinline__ void zacc(float acc[2][4][4]) {
#pragma unroll
    for (int i = 0; i < 2; ++i)
#pragma unroll
        for (int j = 0; j < 4; ++j)
#pragma unroll
            for (int k = 0; k < 4; ++k) acc[i][j][k] = 0.f;
}
template <int KSTEPS>
__device__ __forceinline__ void wgemm(uint32_t aA0, uint32_t aA1,
                                      const uint32_t bA[2], float acc[2][4][4]) {
#pragma unroll
    for (int ks = 0; ks < KSTEPS; ++ks) {
        uint32_t a0[4], a1[4];
        ldsm4(a0, aA0 + ks * 32);
        ldsm4(a1, aA1 + ks * 32);
#pragma unroll
        for (int jj = 0; jj < 2; ++jj) {
            uint32_t b[4];
            ldsm4(b, bA[jj] + ks * 32);
            mma16(acc[0][2 * jj],     a0, b[0], b[1]);
            mma16(acc[0][2 * jj + 1], a0, b[2], b[3]);
            mma16(acc[1][2 * jj],     a1, b[0], b[1]);
            mma16(acc[1][2 * jj + 1], a1, b[2], b[3]);
        }
    }
}

__device__ __forceinline__ void stage_chunk256(uint32_t dstB, const __half* srcBase,
                                               int srcK, int tid) {
#pragma unroll
    for (int i = tid; i < 128 * 8; i += 256) {
        int n = i >> 3, k8 = (i & 7) * 8;
        CP16(dstB + (uint32_t)(n * SB_STR + k8 * 2),
             srcBase + (size_t)n * srcK + k8);
    }
}
template <int KH>
__device__ __forceinline__ void stage_w(uint32_t dstB, int dstStr,
                                        const __half* srcBase, int srcK, int tid) {
    constexpr int SEGS = KH / 8;
#pragma unroll
    for (int i = tid; i < 128 * SEGS; i += 512) {
        int n = i / SEGS, s = i % SEGS;
        CP16(dstB + (uint32_t)(n * dstStr + s * 16),
             srcBase + (size_t)n * srcK + s * 8);
    }
}

// ---------------------------------------------------------------------------
// Prep: transposes + fp16 + the eW@W1b fusion
// ---------------------------------------------------------------------------
__global__ void k_tW(const float* __restrict__ nW, const float* __restrict__ eW,
                     const float* __restrict__ eb, const float* __restrict__ W1,
                     const float* __restrict__ b1, const float* __restrict__ W2,
                     const float* __restrict__ U1, const float* __restrict__ U2) {
    int t = blockIdx.x * blockDim.x + threadIdx.x;
    int tot = gridDim.x * blockDim.x;
    for (int i = t; i < 128 * 128; i += tot) {
        int n = i >> 7, k = i & 127;
        g_nWt[i] = __float2half_rn(nW[k * 128 + n]);
        g_W2t[i] = __float2half_rn(W2[k * 128 + n]);
        g_U2t[i] = __float2half_rn(U2[k * 128 + n]);
    }
    for (int i = t; i < 128 * 256; i += tot) {
        int n = i >> 8, k = i & 255;
        g_W1t[i] = __float2half_rn(W1[k * 128 + n]);
        g_U1t[i] = __float2half_rn(U1[k * 128 + n]);
    }
    // W1e^T[n][kf] = sum_j eW[kf][j] * W1[128+j][n]   (fp32 accum)
    for (int i = t; i < 128 * 64; i += tot) {
        int n = i >> 6, kf = i & 63;
        float s = 0.f;
#pragma unroll 4
        for (int j = 0; j < 128; ++j)
            s = fmaf(eW[kf * 128 + j], W1[(128 + j) * 128 + n], s);
        g_W1et[i] = __float2half_rn(s);
    }
    // b1'[n] = b1[n] + sum_j eb[j] * W1[128+j][n]
    for (int i = t; i < 128; i += tot) {
        float s = b1[i];
#pragma unroll 4
        for (int j = 0; j < 128; ++j)
            s = fmaf(eb[j], W1[(128 + j) * 128 + i], s);
        g_b1p[i] = s;
    }
}

__global__ __launch_bounds__(256) void k_zero_agg() {
    size_t i = (size_t)blockIdx.x * 256 + threadIdx.x;
    reinterpret_cast<float4*>(g_agg)[i] = make_float4(0.f, 0.f, 0.f, 0.f);
}

// ---------------------------------------------------------------------------
// Kernel 1: h = fp16(node_feats @ node_W + node_b) -> g_h   (512 thr)
// ---------------------------------------------------------------------------
static constexpr int NODE_SA = 0;
static constexpr int NODE_SB = 128 * SA_STR;
static constexpr int NODE_BIAS = NODE_SB + 128 * SA_STR;
static constexpr int NODE_SMEM = NODE_BIAS + 512;

__global__ __launch_bounds__(512, 1) void k_node(const float* __restrict__ nf,
                                                 const float* __restrict__ b) {
    char* smem = dyn_smem;
    float* sBias = reinterpret_cast<float*>(smem + NODE_BIAS);
    const uint32_t sb0 = smem_u32(smem);
    const int tid = threadIdx.x, lane = tid & 31, w = tid >> 5;
    const int base = blockIdx.x * 128;

    if (tid < 128) sBias[tid] = b[tid];
    for (int i = tid; i < 128 * 32; i += 512) {
        int r = i >> 5, c = (i & 31) * 4;
        int gr = base + r;
        float4 v = make_float4(0.f, 0.f, 0.f, 0.f);
        if (gr < NN) v = *reinterpret_cast<const float4*>(nf + (size_t)gr * HID + c);
        __half2* p = reinterpret_cast<__half2*>(smem + NODE_SA + r * SA_STR + c * 2);
        p[0] = __floats2half2_rn(v.x, v.y);
        p[1] = __floats2half2_rn(v.z, v.w);
    }
    for (int i = tid; i < 128 * 16; i += 512) {
        int r = i >> 4, s = (i & 15);
        *reinterpret_cast<float4*>(smem + NODE_SB + r * SA_STR + s * 16) =
            *reinterpret_cast<const float4*>(
                reinterpret_cast<const char*>(g_nWt) + (size_t)r * 256 + s * 16);
    }
    __syncthreads();

    const int mb = (w & 3) * 32, nb = (w >> 2) * 32;
    uint32_t aA0 = sb0 + NODE_SA + (uint32_t)mb * SA_STR + a_off(lane, SA_STR);
    uint32_t aA1 = aA0 + 16 * SA_STR;
    uint32_t bA[2];
#pragma unroll
    for (int jj = 0; jj < 2; ++jj)
        bA[jj] = sb0 + NODE_SB + (uint32_t)(nb + jj * 16) * SA_STR + b_off(lane, SA_STR);

    float acc[2][4][4];
    zacc(acc);
    wgemm<8>(aA0, aA1, bA, acc);

    const int g = lane >> 2, tg = lane & 3;
#pragma unroll
    for (int i = 0; i < 2; ++i) {
        int r0 = base + mb + i * 16 + g;
#pragma unroll
        for (int j = 0; j < 4; ++j) {
            int c = nb + j * 8 + 2 * tg;
            if (r0 < NN)
                *reinterpret_cast<__half2*>(g_h + (size_t)r0 * HID + c) =
                    __floats2half2_rn(acc[i][j][0] + sBias[c], acc[i][j][1] + sBias[c + 1]);
            if (r0 + 8 < NN)
                *reinterpret_cast<__half2*>(g_h + (size_t)(r0 + 8) * HID + c) =
                    __floats2half2_rn(acc[i][j][2] + sBias[c], acc[i][j][3] + sBias[c + 1]);
        }
    }
}

// ---------------------------------------------------------------------------
// Kernel 2: fused edge pipeline with eW@W1b folded into W1e.
//   t = relu(h@W1a + ef@W1e + b1') ; m = t@W2 + b2 ; scatter-add.
// 256 threads, 2 CTAs/SM, 64x32 warp tiles, 5 streamed K=64 chunks.
// smem: sH (h then t) | sEF | B0 | B1 | misc  = 91648 B
// ---------------------------------------------------------------------------
static constexpr int SH_B  = 0;
static constexpr int EF_B  = 34816;
static constexpr int B0_B  = EF_B + 128 * EF_STR;      // 53248
static constexpr int B1_B  = B0_B + 128 * SB_STR;      // 71680
static constexpr int MISC_B = B1_B + 128 * SB_STR;     // 90112
static constexpr int EDGE_SMEM = MISC_B + 3 * 128 * 4; // 91648

__global__ __launch_bounds__(256, 2) void k_edge(const int* __restrict__ eidx,
                                                 const float* __restrict__ ef,
                                                 const float* __restrict__ b2) {
    char* smem = dyn_smem;
    float* sB1p = reinterpret_cast<float*>(smem + MISC_B);
    float* sB2b = sB1p + 128;
    int* sDst = reinterpret_cast<int*>(sB2b + 128);
    const uint32_t sb0 = smem_u32(smem);

    const int tid = threadIdx.x, lane = tid & 31, w = tid >> 5;
    const int e0 = blockIdx.x * 128;

    if (tid < 128) {
        sDst[tid] = eidx[NE + e0 + tid];
        sB1p[tid] = g_b1p[tid];
    } else {
        sB2b[tid - 128] = b2[tid - 128];
    }

    // g0: gather h[src] -> sH
#pragma unroll
    for (int i = tid; i < 128 * 16; i += 256) {
        int r = i >> 4, s = i & 15;
        int src = eidx[e0 + r];
        CP16(sb0 + SH_B + (uint32_t)(r * SA_STR + s * 16),
             g_h + (size_t)src * HID + s * 8);
    }
    CP_COMMIT();
    // g1: c1 = W1a[:,0:64] -> B0
    stage_chunk256(sb0 + B0_B, g_W1t, 256, tid);
    CP_COMMIT();
    // g2: c2 = W1a[:,64:128] -> B1
    stage_chunk256(sb0 + B1_B, g_W1t + 64, 256, tid);
    CP_COMMIT();

    // ef [128x64] fp32 -> fp16 into sEF
#pragma unroll
    for (int i = tid; i < 128 * 16; i += 256) {
        int r = i >> 4, c = (i & 15) * 4;
        float4 v = *reinterpret_cast<const float4*>(ef + (size_t)(e0 + r) * 64 + c);
        __half2* p = reinterpret_cast<__half2*>(smem + EF_B + r * EF_STR + c * 2);
        p[0] = __floats2half2_rn(v.x, v.y);
        p[1] = __floats2half2_rn(v.z, v.w);
    }

    // warp tiling: 2 (M) x 4 (N) warps, 64x32 each
    const int mb = (w & 1) * 64, nb = (w >> 1) * 32;
    uint32_t aH[4], aF[4];
#pragma unroll
    for (int m = 0; m < 4; ++m) {
        aH[m] = sb0 + SH_B + (uint32_t)(mb + m * 16) * SA_STR + a_off(lane, SA_STR);
        aF[m] = sb0 + EF_B + (uint32_t)(mb + m * 16) * EF_STR + a_off(lane, EF_STR);
    }
    uint32_t b0A[2], b1A[2];
#pragma unroll
    for (int jj = 0; jj < 2; ++jj) {
        uint32_t off = (uint32_t)(nb + jj * 16) * SB_STR + b_off(lane, SB_STR);
        b0A[jj] = sb0 + B0_B + off;
        b1A[jj] = sb0 + B1_B + off;
    }

    const int g = lane >> 2, tg = lane & 3;
    float acc[4][4][4];

    // ---- GEMM1: t_acc = h@W1a + ef@W1e  (3 K=64 chunks) ----
    CP_WAIT(1);          // g0 (gather) + g1 (c1) complete
    __syncthreads();     // publish sH, c1, ef, biases
    zacc64(acc);
    wgemm64<4>(aH, b0A, acc);                       // c1: h k0:64

    CP_WAIT(0);          // c2 complete
    __syncthreads();     // publish c2; B0 free
    stage_chunk256(sb0 + B0_B, g_W1et, 64, tid);    // c3 = W1e -> B0
    CP_COMMIT();
    {
        uint32_t aH2[4] = {aH[0] + 128, aH[1] + 128, aH[2] + 128, aH[3] + 128};
        wgemm64<4>(aH2, b1A, acc);                  // c2: h k64:128
    }
    CP_WAIT(0);
    __syncthreads();     // publish c3; B1 free; all h reads done
    stage_chunk256(sb0 + B1_B, g_W2t, 128, tid);    // c4 = W2[:,0:64] -> B1
    CP_COMMIT();
    wgemm64<4>(aF, b0A, acc);                       // c3: ef @ W1e (K=64)
    CP_WAIT(0);
    __syncthreads();     // publish c4; B0 free
    stage_chunk256(sb0 + B0_B, g_W2t + 64, 128, tid);  // c5 = W2[:,64:128] -> B0
    CP_COMMIT();

    // epilogue: t = relu(acc + b1') -> sH (h fully consumed at c2)
#pragma unroll
    for (int m = 0; m < 4; ++m) {
        int r0 = mb + m * 16 + g;
#pragma unroll
        for (int j = 0; j < 4; ++j) {
            int c = nb + j * 8 + 2 * tg;
            *reinterpret_cast<__half2*>(smem + SH_B + r0 * SA_STR + c * 2) =
                __floats2half2_rn(fmaxf(acc[m][j][0] + sB1p[c], 0.f),
                                  fmaxf(acc[m][j][1] + sB1p[c + 1], 0.f));
            *reinterpret_cast<__half2*>(smem + SH_B + (r0 + 8) * SA_STR + c * 2) =
                __floats2half2_rn(fmaxf(acc[m][j][2] + sB1p[c], 0.f),
                                  fmaxf(acc[m][j][3] + sB1p[c + 1], 0.f));
        }
    }
    __syncthreads();     // publish t

    // ---- GEMM2: m = t @ W2 (K=128) ----
    zacc64(acc);
    wgemm64<4>(aH, b1A, acc);                       // c4: t k0:64
    CP_WAIT(0);
    __syncthreads();     // publish c5
    {
        uint32_t aH2[4] = {aH[0] + 128, aH[1] + 128, aH[2] + 128, aH[3] + 128};
        wgemm64<4>(aH2, b0A, acc);                  // c5: t k64:128
    }

    // scalar-atomic scatter into g_agg[dst]
#pragma unroll
    for (int m = 0; m < 4; ++m) {
        int r0 = mb + m * 16 + g;
        float* p0 = g_agg + (size_t)sDst[r0] * HID;
        float* p1 = g_agg + (size_t)sDst[r0 + 8] * HID;
#pragma unroll
        for (int j = 0; j < 4; ++j) {
            int c = nb + j * 8 + 2 * tg;
            atomicAdd(p0 + c, acc[m][j][0] + sB2b[c]);
            atomicAdd(p0 + c + 1, acc[m][j][1] + sB2b[c + 1]);
            atomicAdd(p1 + c, acc[m][j][2] + sB2b[c]);
            atomicAdd(p1 + c + 1, acc[m][j][3] + sB2b[c + 1]);
        }
    }
}

// ---------------------------------------------------------------------------
// Kernel 3: out = relu([nf|agg] @ U1 + ub1) @ U2 + ub2   (512 thr)
// ---------------------------------------------------------------------------
static constexpr int UPD_SH = 0;
static constexpr int UPD_SE = 128 * SA_STR;
static constexpr int UPD_U1 = 2 * 128 * SA_STR;
static constexpr int UPD_U2 = UPD_U1 + 128 * W1_STR;
static constexpr int UPD_B1 = UPD_U2 + 128 * W2_STR;
static constexpr int UPD_B2 = UPD_B1 + 512;
static constexpr int UPD_SMEM = UPD_B2 + 512;

__global__ __launch_bounds__(512, 1) void k_update(const float* __restrict__ nf,
                                                   const float* __restrict__ b1,
                                                   const float* __restrict__ b2,
                                                   float* __restrict__ out) {
    char* smem = dyn_smem;
    float* sB1 = reinterpret_cast<float*>(smem + UPD_B1);
    float* sB2 = reinterpret_cast<float*>(smem + UPD_B2);
    const uint32_t sb0 = smem_u32(smem);

    const int tid = threadIdx.x, lane = tid & 31, w = tid >> 5;
    const int base = blockIdx.x * 128;

    if (tid < 128) {
        sB1[tid] = b1[tid];
        sB2[tid] = b2[tid];
    }
    stage_w<256>(sb0 + UPD_U1, W1_STR, g_U1t, 256, tid);
    stage_w<128>(sb0 + UPD_U2, W2_STR, g_U2t, 128, tid);
    CP_COMMIT();

    for (int i = tid; i < 128 * 32; i += 512) {
        int r = i >> 5, c = (i & 31) * 4;
        int gr = base + r;
        float4 v0 = make_float4(0.f, 0.f, 0.f, 0.f), v1 = v0;
        if (gr < NN) {
            v0 = *reinterpret_cast<const float4*>(nf + (size_t)gr * HID + c);
            v1 = *reinterpret_cast<const float4*>(g_agg + (size_t)gr * HID + c);
        }
        __half2* p0 = reinterpret_cast<__half2*>(smem + UPD_SH + r * SA_STR + c * 2);
        p0[0] = __floats2half2_rn(v0.x, v0.y);
        p0[1] = __floats2half2_rn(v0.z, v0.w);
        __half2* p1 = reinterpret_cast<__half2*>(smem + UPD_SE + r * SA_STR + c * 2);
        p1[0] = __floats2half2_rn(v1.x, v1.y);
        p1[1] = __floats2half2_rn(v1.z, v1.w);
    }
    CP_WAIT(0);
    __syncthreads();

    const int mb = (w & 3) * 32, nb = (w >> 2) * 32;
    uint32_t aH0 = sb0 + UPD_SH + (uint32_t)mb * SA_STR + a_off(lane, SA_STR);
    uint32_t aH1 = aH0 + 16 * SA_STR;
    uint32_t aE0 = sb0 + UPD_SE + (uint32_t)mb * SA_STR + a_off(lane, SA_STR);
    uint32_t aE1 = aE0 + 16 * SA_STR;
    uint32_t bU1[2], bU2[2];
#pragma unroll
    for (int jj = 0; jj < 2; ++jj) {
        int nrow = nb + jj * 16;
        bU1[jj] = sb0 + UPD_U1 + (uint32_t)nrow * W1_STR + b_off(lane, W1_STR);
        bU2[jj] = sb0 + UPD_U2 + (uint32_t)nrow * W2_STR + b_off(lane, W2_STR);
    }

    const int g = lane >> 2, tg = lane & 3;
    float acc[2][4][4];

    zacc(acc);
    wgemm<8>(aH0, aH1, bU1, acc);
    {
        uint32_t bU1hi[2] = {bU1[0] + 256, bU1[1] + 256};
        wgemm<8>(aE0, aE1, bU1hi, acc);
    }
    __syncthreads();
#pragma unroll
    for (int i = 0; i < 2; ++i) {
        int r0 = mb + i * 16 + g;
#pragma unroll
        for (int j = 0; j < 4; ++j) {
            int c = nb + j * 8 + 2 * tg;
            *reinterpret_cast<__half2*>(smem + UPD_SH + r0 * SA_STR + c * 2) =
                __floats2half2_rn(fmaxf(acc[i][j][0] + sB1[c], 0.f),
                                  fmaxf(acc[i][j][1] + sB1[c + 1], 0.f));
            *reinterpret_cast<__half2*>(smem + UPD_SH + (r0 + 8) * SA_STR + c * 2) =
                __floats2half2_rn(fmaxf(acc[i][j][2] + sB1[c], 0.f),
                                  fmaxf(acc[i][j][3] + sB1[c + 1], 0.f));
        }
    }
    __syncthreads();

    zacc(acc);
    wgemm<8>(aH0, aH1, bU2, acc);
#pragma unroll
    for (int i = 0; i < 2; ++i) {
        int r0 = base + mb + i * 16 + g;
#pragma unroll
        for (int j = 0; j < 4; ++j) {
            int c = nb + j * 8 + 2 * tg;
            if (r0 < NN)
                *reinterpret_cast<float2*>(out + (size_t)r0 * HID + c) =
                    make_float2(acc[i][j][0] + sB2[c], acc[i][j][1] + sB2[c + 1]);
            if (r0 + 8 < NN)
                *reinterpret_cast<float2*>(out + (size_t)(r0 + 8) * HID + c) =
                    make_float2(acc[i][j][2] + sB2[c], acc[i][j][3] + sB2[c + 1]);
        }
    }
}

// ---------------------------------------------------------------------------
extern "C" void kernel_launch(void* const* d_in, const int* in_sizes, int n_in,
                              void* d_out, int out_size) {
    const float* node_feats = (const float*)d_in[0];
    const int*   edge_idx   = (const int*)d_in[1];
    const float* edge_feats = (const float*)d_in[2];
    const float* node_W     = (const float*)d_in[3];
    const float* node_b     = (const float*)d_in[4];
    const float* edge_W     = (const float*)d_in[5];
    const float* edge_b     = (const float*)d_in[6];
    const float* msg_W1     = (const float*)d_in[7];
    const float* msg_b1     = (const float*)d_in[8];
    const float* msg_W2     = (const float*)d_in[9];
    const float* msg_b2     = (const float*)d_in[10];
    const float* upd_W1     = (const float*)d_in[11];
    const float* upd_b1     = (const float*)d_in[12];
    const float* upd_W2     = (const float*)d_in[13];
    const float* upd_b2     = (const float*)d_in[14];
    float* out = (float*)d_out;

    cudaFuncSetAttribute(k_node,   cudaFuncAttributeMaxDynamicSharedMemorySize, NODE_SMEM);
    cudaFuncSetAttribute(k_edge,   cudaFuncAttributeMaxDynamicSharedMemorySize, EDGE_SMEM);
    cudaFuncSetAttribute(k_update, cudaFuncAttributeMaxDynamicSharedMemorySize, UPD_SMEM);

    const int NB_NODE = (NN + 127) / 128;  // 391
    const int NB_EDGE = NE / 128;          // 6250

    k_tW<<<128, 256>>>(node_W, edge_W, edge_b, msg_W1, msg_b1, msg_W2,
                       upd_W1, upd_W2);
    k_zero_agg<<<NN * HID / 4 / 256, 256>>>();
    k_node<<<NB_NODE, 512, NODE_SMEM>>>(node_feats, node_b);
    k_edge<<<NB_EDGE, 256, EDGE_SMEM>>>(edge_idx, edge_feats, msg_b2);
    k_update<<<NB_NODE, 512, UPD_SMEM>>>(node_feats, upd_b1, upd_b2, out);
}